// round 7
// baseline (speedup 1.0000x reference)
#include <cuda_runtime.h>
#include <cuda_bf16.h>

#define NN 4096
#define IN_DIM 6
#define HID 32
#define HEADS1 4
#define F1 128          // HEADS1*HID
#define OUT_DIM 64
#define MAXDEG 256      // mean deg ~41 (1% of 4096 + self), 256 is >30 sigma safe
#define K4_NT 8         // nodes per block in k4

// ---------------- device scratch (no allocations allowed) ----------------
__device__ float g_h1raw[NN * F1];
__device__ float g_e_src1[NN * HEADS1];
__device__ float g_e_dst1[NN * HEADS1];
__device__ float g_h1[NN * F1];
__device__ float g_h2raw[NN * OUT_DIM];
__device__ float g_e_src2[NN];
__device__ float g_e_dst2[NN];
__device__ int   g_deg[NN];
__device__ int   g_cols[NN * MAXDEG];

// ---------------- K1: h1raw = x @ W1 ; e_src1/e_dst1 ----------------
// grid NN, block 128. thread c owns output feature c (head=c/32, d=c%32).
__global__ void k1_proj1(const float* __restrict__ x,
                         const float* __restrict__ W1,
                         const float* __restrict__ a_src,
                         const float* __restrict__ a_dst) {
    int n = blockIdx.x;
    int c = threadIdx.x;
    __shared__ float xs[IN_DIM];
    if (c < IN_DIM) xs[c] = x[n * IN_DIM + c];
    __syncthreads();

    float hv = 0.f;
#pragma unroll
    for (int k = 0; k < IN_DIM; k++) hv += xs[k] * W1[k * F1 + c];
    g_h1raw[n * F1 + c] = hv;

    // per-head dot: warp w == head w (32 lanes == HID)
    float ps = hv * a_src[c];   // a_src flat [4*32] indexed by c
    float pd = hv * a_dst[c];
#pragma unroll
    for (int off = 16; off; off >>= 1) {
        ps += __shfl_down_sync(0xffffffffu, ps, off);
        pd += __shfl_down_sync(0xffffffffu, pd, off);
    }
    if ((c & 31) == 0) {
        int h = c >> 5;
        g_e_src1[n * HEADS1 + h] = ps;
        g_e_dst1[n * HEADS1 + h] = pd;
    }
}

// ---------------- K2: deterministic CSR build from dense adj ----------------
// grid NN, block 256. float4 loads: 4096 floats = 1024 float4 per row,
// thread t handles float4 chunks t, t+256, t+512, t+768 (4 iterations).
// Block prefix-sum of per-thread counts -> ordered, atomic-free compaction.
__global__ void k2_csr(const float* __restrict__ adj) {
    int i = blockIdx.x;
    int t = threadIdx.x;
    const float4* row4 = (const float4*)(adj + (size_t)i * NN);

    // pass 1: count
    int cnt = 0;
#pragma unroll
    for (int it = 0; it < 4; it++) {
        int q = t + it * 256;               // float4 index, 0..1023
        float4 v = row4[q];
        int j0 = q * 4;
        if (v.x > 0.f || j0 + 0 == i) cnt++;
        if (v.y > 0.f || j0 + 1 == i) cnt++;
        if (v.z > 0.f || j0 + 2 == i) cnt++;
        if (v.w > 0.f || j0 + 3 == i) cnt++;
    }

    __shared__ int s[256];
    s[t] = cnt;
    __syncthreads();
    // Hillis-Steele inclusive scan
    for (int off = 1; off < 256; off <<= 1) {
        int v = (t >= off) ? s[t - off] : 0;
        __syncthreads();
        s[t] += v;
        __syncthreads();
    }
    int total = s[255];
    int base = s[t] - cnt;   // exclusive prefix

    // pass 2: compaction in identical traversal order (L2-hot re-read)
    int w = 0;
#pragma unroll
    for (int it = 0; it < 4; it++) {
        int q = t + it * 256;
        float4 v = row4[q];
        int j0 = q * 4;
        float f[4] = {v.x, v.y, v.z, v.w};
#pragma unroll
        for (int u = 0; u < 4; u++) {
            if (f[u] > 0.f || j0 + u == i) {
                int slot = base + w;
                if (slot < MAXDEG) g_cols[i * MAXDEG + slot] = j0 + u;
                w++;
            }
        }
    }
    if (t == 0) g_deg[i] = (total < MAXDEG) ? total : MAXDEG;
}

// ---------------- K3: layer-1 sparse attention + aggregate + bias + ELU ----
// grid NN, block 128. thread c owns output feature c.
__global__ void k3_attn1(const float* __restrict__ b1) {
    int n = blockIdx.x;
    int t = threadIdx.x;
    int deg = g_deg[n];

    __shared__ int   cols_s[MAXDEG];
    __shared__ float w_s[MAXDEG * HEADS1];
    __shared__ float sinv[HEADS1];

    // pass A: logits per (neighbor, head), neighbors strided over 128 threads
    float es[HEADS1];
#pragma unroll
    for (int h = 0; h < HEADS1; h++) es[h] = g_e_src1[n * HEADS1 + h];

    for (int nbr = t; nbr < deg; nbr += 128) {
        int j = g_cols[n * MAXDEG + nbr];
        cols_s[nbr] = j;
#pragma unroll
        for (int h = 0; h < HEADS1; h++) {
            float l = es[h] + g_e_dst1[j * HEADS1 + h];
            l = (l > 0.f) ? l : 0.2f * l;           // leaky_relu(0.2)
            w_s[nbr * HEADS1 + h] = l;
        }
    }
    __syncthreads();

    // warp h reduces head h: max, then exp+sum in place
    int h = t >> 5, lane = t & 31;
    {
        float m = -1e30f;
        for (int nbr = lane; nbr < deg; nbr += 32)
            m = fmaxf(m, w_s[nbr * HEADS1 + h]);
#pragma unroll
        for (int off = 16; off; off >>= 1)
            m = fmaxf(m, __shfl_xor_sync(0xffffffffu, m, off));
        float ssum = 0.f;
        for (int nbr = lane; nbr < deg; nbr += 32) {
            float e = expf(w_s[nbr * HEADS1 + h] - m);
            w_s[nbr * HEADS1 + h] = e;
            ssum += e;
        }
#pragma unroll
        for (int off = 16; off; off >>= 1)
            ssum += __shfl_xor_sync(0xffffffffu, ssum, off);
        if (lane == 0) sinv[h] = 1.f / ssum;
    }
    __syncthreads();

    // pass B: weighted aggregation over neighbors (coalesced 512B per nbr)
    int head = t >> 5;
    float acc = 0.f;
    for (int nbr = 0; nbr < deg; nbr++) {
        acc += w_s[nbr * HEADS1 + head] * g_h1raw[cols_s[nbr] * F1 + t];
    }
    float o = acc * sinv[head] + b1[t];
    o = (o > 0.f) ? o : (expf(o) - 1.f);            // ELU alpha=1
    g_h1[n * F1 + t] = o;
}

// ---------------- K4 v2: h2raw = h1 @ W2 ; e_src2/e_dst2 ----------------
// grid NN/K4_NT = 512, block 64. Each block processes K4_NT=8 nodes so every
// W2 element is loaded ONCE per 8 nodes (8x LDG reduction vs v1).
// hs staged in smem, read as broadcast float4 (conflict-free).
__global__ void k4_proj2(const float* __restrict__ W2,
                         const float* __restrict__ a_src2,
                         const float* __restrict__ a_dst2) {
    int n0 = blockIdx.x * K4_NT;
    int c = threadIdx.x;            // 0..63, output feature

    __shared__ float hs[K4_NT * F1];   // 4 KB
    for (int idx = c; idx < K4_NT * F1; idx += 64)
        hs[idx] = g_h1[n0 * F1 + idx];
    __syncthreads();

    float acc[K4_NT];
#pragma unroll
    for (int tn = 0; tn < K4_NT; tn++) acc[tn] = 0.f;

    // k in blocks of 4: 4 LDG (W2) + 8 LDS.128 (broadcast) + 32 FFMA
    for (int kk = 0; kk < F1; kk += 4) {
        float w0 = W2[(kk + 0) * OUT_DIM + c];
        float w1 = W2[(kk + 1) * OUT_DIM + c];
        float w2 = W2[(kk + 2) * OUT_DIM + c];
        float w3 = W2[(kk + 3) * OUT_DIM + c];
#pragma unroll
        for (int tn = 0; tn < K4_NT; tn++) {
            float4 h4 = *(const float4*)&hs[tn * F1 + kk];
            acc[tn] += h4.x * w0 + h4.y * w1 + h4.z * w2 + h4.w * w3;
        }
    }

    float asc = a_src2[c], adc = a_dst2[c];
    __shared__ float rs[2], rd[2];
#pragma unroll
    for (int tn = 0; tn < K4_NT; tn++) {
        g_h2raw[(n0 + tn) * OUT_DIM + c] = acc[tn];
        float ps = acc[tn] * asc;
        float pd = acc[tn] * adc;
#pragma unroll
        for (int off = 16; off; off >>= 1) {
            ps += __shfl_down_sync(0xffffffffu, ps, off);
            pd += __shfl_down_sync(0xffffffffu, pd, off);
        }
        if ((c & 31) == 0) { rs[c >> 5] = ps; rd[c >> 5] = pd; }
        __syncthreads();
        if (c == 0) {
            g_e_src2[n0 + tn] = rs[0] + rs[1];
            g_e_dst2[n0 + tn] = rd[0] + rd[1];
        }
        __syncthreads();
    }
}

// ---------------- K5: layer-2 sparse attention + bias -> out ----------------
// grid NN, block 64.
__global__ void k5_attn2(const float* __restrict__ b2,
                         float* __restrict__ out) {
    int n = blockIdx.x;
    int t = threadIdx.x;
    int deg = g_deg[n];

    __shared__ int   cols_s[MAXDEG];
    __shared__ float w_s[MAXDEG];
    __shared__ float sinv_s;

    float es = g_e_src2[n];
    for (int nbr = t; nbr < deg; nbr += 64) {
        int j = g_cols[n * MAXDEG + nbr];
        cols_s[nbr] = j;
        float l = es + g_e_dst2[j];
        l = (l > 0.f) ? l : 0.2f * l;
        w_s[nbr] = l;
    }
    __syncthreads();

    // warp 0 reduces: max, exp, sum
    if (t < 32) {
        float m = -1e30f;
        for (int nbr = t; nbr < deg; nbr += 32) m = fmaxf(m, w_s[nbr]);
#pragma unroll
        for (int off = 16; off; off >>= 1)
            m = fmaxf(m, __shfl_xor_sync(0xffffffffu, m, off));
        float ssum = 0.f;
        for (int nbr = t; nbr < deg; nbr += 32) {
            float e = expf(w_s[nbr] - m);
            w_s[nbr] = e;
            ssum += e;
        }
#pragma unroll
        for (int off = 16; off; off >>= 1)
            ssum += __shfl_xor_sync(0xffffffffu, ssum, off);
        if (t == 0) sinv_s = 1.f / ssum;
    }
    __syncthreads();

    float inv = sinv_s;
    float acc = 0.f;
    for (int nbr = 0; nbr < deg; nbr++) {
        acc += w_s[nbr] * g_h2raw[cols_s[nbr] * OUT_DIM + t];
    }
    out[n * OUT_DIM + t] = acc * inv + b2[t];
}

// ---------------- launch ----------------
extern "C" void kernel_launch(void* const* d_in, const int* in_sizes, int n_in,
                              void* d_out, int out_size) {
    const float* x      = (const float*)d_in[0];
    const float* adj    = (const float*)d_in[1];
    const float* W1     = (const float*)d_in[2];
    const float* a_src1 = (const float*)d_in[3];
    const float* a_dst1 = (const float*)d_in[4];
    const float* b1     = (const float*)d_in[5];
    const float* W2     = (const float*)d_in[6];
    const float* a_src2 = (const float*)d_in[7];
    const float* a_dst2 = (const float*)d_in[8];
    const float* b2     = (const float*)d_in[9];
    float* out = (float*)d_out;

    k1_proj1<<<NN, 128>>>(x, W1, a_src1, a_dst1);
    k2_csr<<<NN, 256>>>(adj);
    k3_attn1<<<NN, 128>>>(b1);
    k4_proj2<<<NN / K4_NT, 64>>>(W2, a_src2, a_dst2);
    k5_attn2<<<NN, 64>>>(b2, out);
}

// round 9
// speedup vs baseline: 1.0012x; 1.0012x over previous
#include <cuda_runtime.h>
#include <cuda_bf16.h>

#define NN 4096
#define IN_DIM 6
#define HID 32
#define HEADS1 4
#define F1 128          // HEADS1*HID
#define OUT_DIM 64
#define MAXDEG 256      // mean deg ~41 (1% of 4096 + self), 256 is >30 sigma safe
#define K4_NT 16        // nodes per block in k4 (4 groups x 4 nodes)

// ---------------- device scratch (no allocations allowed) ----------------
__device__ float g_h1raw[NN * F1];
__device__ float g_e_src1[NN * HEADS1];
__device__ float g_e_dst1[NN * HEADS1];
__device__ float g_h1[NN * F1];
__device__ float g_h2raw[NN * OUT_DIM];
__device__ float g_e_src2[NN];
__device__ float g_e_dst2[NN];
__device__ int   g_deg[NN];
__device__ int   g_cols[NN * MAXDEG];
__device__ float g_wa_src[F1];   // W2 @ a_src2
__device__ float g_wa_dst[F1];   // W2 @ a_dst2

// ---------------- K0: wa_src = W2 @ a_src2 ; wa_dst = W2 @ a_dst2 --------
// 1 block, 128 threads; thread k owns row k of W2.
__global__ void k0_wa(const float* __restrict__ W2,
                      const float* __restrict__ a_src2,
                      const float* __restrict__ a_dst2) {
    int k = threadIdx.x;
    float s = 0.f, d = 0.f;
#pragma unroll 8
    for (int c = 0; c < OUT_DIM; c++) {
        float w = W2[k * OUT_DIM + c];
        s += w * a_src2[c];
        d += w * a_dst2[c];
    }
    g_wa_src[k] = s;
    g_wa_dst[k] = d;
}

// ---------------- K1: h1raw = x @ W1 ; e_src1/e_dst1 ----------------
// grid NN, block 128. thread c owns output feature c (head=c/32, d=c%32).
__global__ void k1_proj1(const float* __restrict__ x,
                         const float* __restrict__ W1,
                         const float* __restrict__ a_src,
                         const float* __restrict__ a_dst) {
    int n = blockIdx.x;
    int c = threadIdx.x;
    __shared__ float xs[IN_DIM];
    if (c < IN_DIM) xs[c] = x[n * IN_DIM + c];
    __syncthreads();

    float hv = 0.f;
#pragma unroll
    for (int k = 0; k < IN_DIM; k++) hv += xs[k] * W1[k * F1 + c];
    g_h1raw[n * F1 + c] = hv;

    // per-head dot: warp w == head w (32 lanes == HID)
    float ps = hv * a_src[c];   // a_src flat [4*32] indexed by c
    float pd = hv * a_dst[c];
#pragma unroll
    for (int off = 16; off; off >>= 1) {
        ps += __shfl_down_sync(0xffffffffu, ps, off);
        pd += __shfl_down_sync(0xffffffffu, pd, off);
    }
    if ((c & 31) == 0) {
        int h = c >> 5;
        g_e_src1[n * HEADS1 + h] = ps;
        g_e_dst1[n * HEADS1 + h] = pd;
    }
}

// ---------------- K2: deterministic CSR build from dense adj ----------------
// grid NN, block 256, float4 loads; block prefix-sum -> ordered compaction.
__global__ void k2_csr(const float* __restrict__ adj) {
    int i = blockIdx.x;
    int t = threadIdx.x;
    const float4* row4 = (const float4*)(adj + (size_t)i * NN);

    // pass 1: count
    int cnt = 0;
#pragma unroll
    for (int it = 0; it < 4; it++) {
        int q = t + it * 256;               // float4 index, 0..1023
        float4 v = row4[q];
        int j0 = q * 4;
        if (v.x > 0.f || j0 + 0 == i) cnt++;
        if (v.y > 0.f || j0 + 1 == i) cnt++;
        if (v.z > 0.f || j0 + 2 == i) cnt++;
        if (v.w > 0.f || j0 + 3 == i) cnt++;
    }

    __shared__ int s[256];
    s[t] = cnt;
    __syncthreads();
    // Hillis-Steele inclusive scan
    for (int off = 1; off < 256; off <<= 1) {
        int v = (t >= off) ? s[t - off] : 0;
        __syncthreads();
        s[t] += v;
        __syncthreads();
    }
    int total = s[255];
    int base = s[t] - cnt;   // exclusive prefix

    // pass 2: compaction in identical traversal order (L2-hot re-read)
    int w = 0;
#pragma unroll
    for (int it = 0; it < 4; it++) {
        int q = t + it * 256;
        float4 v = row4[q];
        int j0 = q * 4;
        float f[4] = {v.x, v.y, v.z, v.w};
#pragma unroll
        for (int u = 0; u < 4; u++) {
            if (f[u] > 0.f || j0 + u == i) {
                int slot = base + w;
                if (slot < MAXDEG) g_cols[i * MAXDEG + slot] = j0 + u;
                w++;
            }
        }
    }
    if (t == 0) g_deg[i] = (total < MAXDEG) ? total : MAXDEG;
}

// ---------------- K3: layer-1 attention + aggregate + ELU + e2 logits ----
// grid NN, block 128. thread c owns output feature c.
// Also computes e_src2/e_dst2 = h1[n,:] . wa_{src,dst} (epilogue moved here
// from k4 — h1 value is already in register).
__global__ void k3_attn1(const float* __restrict__ b1) {
    int n = blockIdx.x;
    int t = threadIdx.x;
    int deg = g_deg[n];

    __shared__ int   cols_s[MAXDEG];
    __shared__ float w_s[MAXDEG * HEADS1];
    __shared__ float sinv[HEADS1];
    __shared__ float r2[8];   // 4 warps x {src,dst}

    // pass A: logits per (neighbor, head), neighbors strided over 128 threads
    float es[HEADS1];
#pragma unroll
    for (int h = 0; h < HEADS1; h++) es[h] = g_e_src1[n * HEADS1 + h];

    for (int nbr = t; nbr < deg; nbr += 128) {
        int j = g_cols[n * MAXDEG + nbr];
        cols_s[nbr] = j;
#pragma unroll
        for (int h = 0; h < HEADS1; h++) {
            float l = es[h] + g_e_dst1[j * HEADS1 + h];
            l = (l > 0.f) ? l : 0.2f * l;           // leaky_relu(0.2)
            w_s[nbr * HEADS1 + h] = l;
        }
    }
    __syncthreads();

    // warp h reduces head h: max, then exp+sum in place
    int h = t >> 5, lane = t & 31;
    {
        float m = -1e30f;
        for (int nbr = lane; nbr < deg; nbr += 32)
            m = fmaxf(m, w_s[nbr * HEADS1 + h]);
#pragma unroll
        for (int off = 16; off; off >>= 1)
            m = fmaxf(m, __shfl_xor_sync(0xffffffffu, m, off));
        float ssum = 0.f;
        for (int nbr = lane; nbr < deg; nbr += 32) {
            float e = expf(w_s[nbr * HEADS1 + h] - m);
            w_s[nbr * HEADS1 + h] = e;
            ssum += e;
        }
#pragma unroll
        for (int off = 16; off; off >>= 1)
            ssum += __shfl_xor_sync(0xffffffffu, ssum, off);
        if (lane == 0) sinv[h] = 1.f / ssum;
    }
    __syncthreads();

    // pass B: weighted aggregation over neighbors (coalesced 512B per nbr)
    int head = t >> 5;
    float acc = 0.f;
    for (int nbr = 0; nbr < deg; nbr++) {
        acc += w_s[nbr * HEADS1 + head] * g_h1raw[cols_s[nbr] * F1 + t];
    }
    float o = acc * sinv[head] + b1[t];
    o = (o > 0.f) ? o : (expf(o) - 1.f);            // ELU alpha=1
    g_h1[n * F1 + t] = o;

    // layer-2 logit terms: block-reduce o*wa over the 128 features
    float ps = o * g_wa_src[t];
    float pd = o * g_wa_dst[t];
#pragma unroll
    for (int off = 16; off; off >>= 1) {
        ps += __shfl_down_sync(0xffffffffu, ps, off);
        pd += __shfl_down_sync(0xffffffffu, pd, off);
    }
    if (lane == 0) { r2[head] = ps; r2[4 + head] = pd; }
    __syncthreads();
    if (t == 0) {
        g_e_src2[n] = r2[0] + r2[1] + r2[2] + r2[3];
        g_e_dst2[n] = r2[4] + r2[5] + r2[6] + r2[7];
    }
}

// ---------------- K4 v3: pure GEMM h2raw = h1 @ W2 ----------------
// grid NN/K4_NT = 256, block 256 (8 warps). 4 groups of 64 threads; group g
// owns nodes n0+4g..n0+4g+3 with 4 accumulators. W2 element loaded once per
// 16 nodes (4x fewer LDG than v1) at 14 warps/SM (vs v2's 7). No epilogue
// reductions (moved to k3), no syncs after staging.
__global__ void k4_proj2(const float* __restrict__ W2) {
    int n0 = blockIdx.x * K4_NT;
    int t = threadIdx.x;
    int c = t & 63;                 // output feature
    int g = t >> 6;                 // group 0..3

    __shared__ float hs[K4_NT * F1];   // 8 KB
    {
        const float4* src = (const float4*)&g_h1[n0 * F1];
        float4* dst = (float4*)hs;
        dst[t] = src[t];                       // 256 float4 = 4 KB
        dst[t + 256] = src[t + 256];           // next 4 KB
    }
    __syncthreads();

    float acc0 = 0.f, acc1 = 0.f, acc2 = 0.f, acc3 = 0.f;
    const float* hsg = &hs[(g * 4) * F1];

#pragma unroll 4
    for (int kk = 0; kk < F1; kk += 4) {
        float w0 = W2[(kk + 0) * OUT_DIM + c];
        float w1 = W2[(kk + 1) * OUT_DIM + c];
        float w2 = W2[(kk + 2) * OUT_DIM + c];
        float w3 = W2[(kk + 3) * OUT_DIM + c];
        float4 h0 = *(const float4*)&hsg[0 * F1 + kk];
        float4 h1 = *(const float4*)&hsg[1 * F1 + kk];
        float4 h2 = *(const float4*)&hsg[2 * F1 + kk];
        float4 h3 = *(const float4*)&hsg[3 * F1 + kk];
        acc0 += h0.x * w0 + h0.y * w1 + h0.z * w2 + h0.w * w3;
        acc1 += h1.x * w0 + h1.y * w1 + h1.z * w2 + h1.w * w3;
        acc2 += h2.x * w0 + h2.y * w1 + h2.z * w2 + h2.w * w3;
        acc3 += h3.x * w0 + h3.y * w1 + h3.z * w2 + h3.w * w3;
    }

    int nb = n0 + g * 4;
    g_h2raw[(nb + 0) * OUT_DIM + c] = acc0;
    g_h2raw[(nb + 1) * OUT_DIM + c] = acc1;
    g_h2raw[(nb + 2) * OUT_DIM + c] = acc2;
    g_h2raw[(nb + 3) * OUT_DIM + c] = acc3;
}

// ---------------- K5: layer-2 sparse attention + bias -> out ----------------
// grid NN, block 64.
__global__ void k5_attn2(const float* __restrict__ b2,
                         float* __restrict__ out) {
    int n = blockIdx.x;
    int t = threadIdx.x;
    int deg = g_deg[n];

    __shared__ int   cols_s[MAXDEG];
    __shared__ float w_s[MAXDEG];
    __shared__ float sinv_s;

    float es = g_e_src2[n];
    for (int nbr = t; nbr < deg; nbr += 64) {
        int j = g_cols[n * MAXDEG + nbr];
        cols_s[nbr] = j;
        float l = es + g_e_dst2[j];
        l = (l > 0.f) ? l : 0.2f * l;
        w_s[nbr] = l;
    }
    __syncthreads();

    // warp 0 reduces: max, exp, sum
    if (t < 32) {
        float m = -1e30f;
        for (int nbr = t; nbr < deg; nbr += 32) m = fmaxf(m, w_s[nbr]);
#pragma unroll
        for (int off = 16; off; off >>= 1)
            m = fmaxf(m, __shfl_xor_sync(0xffffffffu, m, off));
        float ssum = 0.f;
        for (int nbr = t; nbr < deg; nbr += 32) {
            float e = expf(w_s[nbr] - m);
            w_s[nbr] = e;
            ssum += e;
        }
#pragma unroll
        for (int off = 16; off; off >>= 1)
            ssum += __shfl_xor_sync(0xffffffffu, ssum, off);
        if (t == 0) sinv_s = 1.f / ssum;
    }
    __syncthreads();

    float inv = sinv_s;
    float acc = 0.f;
    for (int nbr = 0; nbr < deg; nbr++) {
        acc += w_s[nbr] * g_h2raw[cols_s[nbr] * OUT_DIM + t];
    }
    out[n * OUT_DIM + t] = acc * inv + b2[t];
}

// ---------------- launch ----------------
extern "C" void kernel_launch(void* const* d_in, const int* in_sizes, int n_in,
                              void* d_out, int out_size) {
    const float* x      = (const float*)d_in[0];
    const float* adj    = (const float*)d_in[1];
    const float* W1     = (const float*)d_in[2];
    const float* a_src1 = (const float*)d_in[3];
    const float* a_dst1 = (const float*)d_in[4];
    const float* b1     = (const float*)d_in[5];
    const float* W2     = (const float*)d_in[6];
    const float* a_src2 = (const float*)d_in[7];
    const float* a_dst2 = (const float*)d_in[8];
    const float* b2     = (const float*)d_in[9];
    float* out = (float*)d_out;

    k0_wa<<<1, F1>>>(W2, a_src2, a_dst2);
    k1_proj1<<<NN, 128>>>(x, W1, a_src1, a_dst1);
    k2_csr<<<NN, 256>>>(adj);
    k3_attn1<<<NN, 128>>>(b1);
    k4_proj2<<<NN / K4_NT, 256>>>(W2);
    k5_attn2<<<NN, 64>>>(b2, out);
}